// round 5
// baseline (speedup 1.0000x reference)
#include <cuda_runtime.h>
#include <cuda_bf16.h>
#include <cstdint>
#include <cstdio>

#define TLTOT 40000
#define NTOP  1000
#define KCDIM 256
#define BM    128
#define BN    64
#define PITCH 264   // bf16 elems per SMEM row (256 + 8 pad -> 528B, 33x16B units, LDSM conflict-free)

#define SMEM_BYTES ((BM*PITCH*2)*2 + (BN*PITCH*2)*2)   // A_hi,A_lo,B_hi,B_lo = 202752

// -log(0.1) - 0.5*log(2*pi)
#define LOGC 1.3836465597893728f

__device__ __nv_bfloat16 g_Bhi[NTOP * KCDIM];
__device__ __nv_bfloat16 g_Blo[NTOP * KCDIM];

// ---------------------------------------------------------------------------
// Kernel 1: column-sums of neighbor_weights, build split-bf16 V_j, zero d_out
// ---------------------------------------------------------------------------
__global__ void setup_kernel(const float* __restrict__ V,
                             const float* __restrict__ nw,
                             const float* __restrict__ noise,
                             float* __restrict__ out)
{
    __shared__ float s_sm[256];
    int t = threadIdx.x;
    int b = blockIdx.x;
    int j = b * 256 + t;

    float s = 0.f;
    if (j < NTOP) {                       // guard: NTOP=1000 < 4*256 threads
        #pragma unroll 8
        for (int i = 0; i < NTOP; i++)
            s += nw[i * NTOP + j];
    }
    s_sm[t] = s;
    __syncthreads();

    for (int idx = t; idx < 256 * KCDIM; idx += 256) {
        int jl = idx >> 8;
        int k  = idx & 255;
        int jg = b * 256 + jl;
        if (jg < NTOP) {                  // guard OOB writes past g_Bhi/g_Blo
            int g = jg * KCDIM + k;
            float v = fmaf(V[g], s_sm[jl], 0.1f * noise[g]);
            __nv_bfloat16 h = __float2bfloat16(v);
            g_Bhi[g] = h;
            g_Blo[g] = __float2bfloat16(v - __bfloat162float(h));
        }
    }
    if (b == 0 && t == 0) *out = 0.f;
}

// ---------------------------------------------------------------------------
// MMA helpers
// ---------------------------------------------------------------------------
__device__ __forceinline__ void ldsm4(uint32_t* r, uint32_t saddr) {
    asm volatile("ldmatrix.sync.aligned.m8n8.x4.shared.b16 {%0,%1,%2,%3}, [%4];\n"
                 : "=r"(r[0]), "=r"(r[1]), "=r"(r[2]), "=r"(r[3]) : "r"(saddr));
}

__device__ __forceinline__ void mma16816(float* c, const uint32_t* a, uint32_t b0, uint32_t b1) {
    asm volatile(
        "mma.sync.aligned.m16n8k16.row.col.f32.bf16.bf16.f32 "
        "{%0,%1,%2,%3},{%4,%5,%6,%7},{%8,%9},{%0,%1,%2,%3};\n"
        : "+f"(c[0]), "+f"(c[1]), "+f"(c[2]), "+f"(c[3])
        : "r"(a[0]), "r"(a[1]), "r"(a[2]), "r"(a[3]), "r"(b0), "r"(b1));
}

__device__ __forceinline__ float sigmoidf(float x) {
    // x may be huge (+/- tens of thousands): exp(-x) -> inf or 0; both map correctly.
    return __fdividef(1.f, 1.f + __expf(-x));
}

// ---------------------------------------------------------------------------
// Kernel 2: fused U_emb + split-bf16 GEMM + sigmoid + masked logprob reduction
// ---------------------------------------------------------------------------
__global__ void __launch_bounds__(256, 1)
main_kernel(const float* __restrict__ R,
            const float* __restrict__ U,
            const float* __restrict__ W,
            const float* __restrict__ Bb,
            const int*   __restrict__ C,
            float* __restrict__ out)
{
    extern __shared__ __align__(16) char smem[];
    __nv_bfloat16* Ah = (__nv_bfloat16*)smem;          // [BM][PITCH]
    __nv_bfloat16* Al = Ah + BM * PITCH;
    __nv_bfloat16* Bh = Al + BM * PITCH;               // [BN][PITCH]
    __nv_bfloat16* Bl = Bh + BN * PITCH;
    __shared__ float red[8];

    const int tid  = threadIdx.x;
    const int lane = tid & 31;
    const int warp = tid >> 5;
    const int wm   = warp & 3;   // 4 warps over M (32 rows each)
    const int wn   = warp >> 2;  // 2 warps over N (32 cols each)
    const int rowbase = blockIdx.x * BM;

    const float w0 = W[0], w1 = W[1], w2 = W[2], w3 = W[3], w4 = W[4];
    const float bb = Bb[0];

    // ---- Phase 1: U_emb (fp32) -> split bf16 A tile ----
    for (int idx = tid; idx < BM * KCDIM; idx += 256) {
        int r = idx >> 8;
        int k = idx & 255;
        int gr = rowbase + r;
        float v = 0.f;
        if (gr < TLTOT) {
            const float* up = U + ((size_t)gr * (KCDIM * 5) + k * 5);
            v = bb;
            v = fmaf(__ldcs(up + 0), w0, v);
            v = fmaf(__ldcs(up + 1), w1, v);
            v = fmaf(__ldcs(up + 2), w2, v);
            v = fmaf(__ldcs(up + 3), w3, v);
            v = fmaf(__ldcs(up + 4), w4, v);
        }
        __nv_bfloat16 h = __float2bfloat16(v);
        Ah[r * PITCH + k] = h;
        Al[r * PITCH + k] = __float2bfloat16(v - __bfloat162float(h));
    }

    // SMEM base addresses for ldmatrix
    const uint32_t sbase = (uint32_t)__cvta_generic_to_shared(smem);
    const uint32_t sAh = sbase;
    const uint32_t sAl = sAh + BM * PITCH * 2;
    const uint32_t sBh = sAl + BM * PITCH * 2;
    const uint32_t sBl = sBh + BN * PITCH * 2;

    // per-lane address components (bytes)
    const uint32_t arow = ((uint32_t)(wm * 32 + (lane & 15)) * PITCH + (uint32_t)(lane >> 4) * 8) * 2;
    const uint32_t boff = ((uint32_t)(wn * 32 + ((lane >> 4) & 1) * 8 + (lane & 7)) * PITCH
                           + (uint32_t)((lane >> 3) & 1) * 8) * 2;

    float lsum = 0.f;

    for (int j0 = 0; j0 < NTOP; j0 += BN) {
        __syncthreads();   // prev iteration's B reads done (also fences phase-1 A writes)

        // ---- load B tiles (16B vectors) ----
        for (int v = tid; v < BN * (KCDIM / 8); v += 256) {   // 2048 chunks
            int n  = v >> 5;
            int c8 = v & 31;
            int jj = j0 + n;
            uint4 hv = make_uint4(0, 0, 0, 0), lv = make_uint4(0, 0, 0, 0);
            if (jj < NTOP) {
                hv = *(const uint4*)(g_Bhi + jj * KCDIM + c8 * 8);
                lv = *(const uint4*)(g_Blo + jj * KCDIM + c8 * 8);
            }
            *(uint4*)(Bh + n * PITCH + c8 * 8) = hv;
            *(uint4*)(Bl + n * PITCH + c8 * 8) = lv;
        }
        __syncthreads();

        // ---- MMA: acc = Ah*Bh + Al*Bh + Ah*Bl (bf16x3 split, ~fp32 accuracy) ----
        float acc[2][4][4] = {};
        #pragma unroll 4
        for (int ks = 0; ks < 16; ks++) {
            const uint32_t k0b = (uint32_t)(ks * 16) * 2;
            uint32_t ah[2][4], al[2][4], bh[2][4], bl[2][4];
            ldsm4(ah[0], sAh + arow + k0b);
            ldsm4(ah[1], sAh + arow + 16 * PITCH * 2 + k0b);
            ldsm4(al[0], sAl + arow + k0b);
            ldsm4(al[1], sAl + arow + 16 * PITCH * 2 + k0b);
            ldsm4(bh[0], sBh + boff + k0b);
            ldsm4(bh[1], sBh + boff + 16 * PITCH * 2 + k0b);
            ldsm4(bl[0], sBl + boff + k0b);
            ldsm4(bl[1], sBl + boff + 16 * PITCH * 2 + k0b);
            #pragma unroll
            for (int mi = 0; mi < 2; mi++) {
                #pragma unroll
                for (int ni = 0; ni < 4; ni++) {
                    const int p = ni >> 1, s = (ni & 1) * 2;
                    mma16816(acc[mi][ni], ah[mi], bh[p][s], bh[p][s + 1]);
                    mma16816(acc[mi][ni], al[mi], bh[p][s], bh[p][s + 1]);
                    mma16816(acc[mi][ni], ah[mi], bl[p][s], bl[p][s + 1]);
                }
            }
        }

        // ---- epilogue: sigmoid + masked Normal logprob ----
        #pragma unroll
        for (int mi = 0; mi < 2; mi++) {
            const int r0 = rowbase + wm * 32 + mi * 16 + (lane >> 2);
            #pragma unroll
            for (int ni = 0; ni < 4; ni++) {
                const int jc = j0 + wn * 32 + ni * 8 + ((lane & 3) << 1);
                if (jc < NTOP) {
                    const float* a = acc[mi][ni];
                    if (r0 < TLTOT) {
                        float2 rv = __ldcs((const float2*)(R + (size_t)r0 * NTOP + jc));
                        int2   cv = __ldcs((const int2*)(C + (size_t)r0 * NTOP + jc));
                        if (cv.x == 1) { float m = sigmoidf(a[0]); float z = (rv.x - m) * 10.f; lsum += LOGC - 0.5f * z * z; }
                        if (cv.y == 1) { float m = sigmoidf(a[1]); float z = (rv.y - m) * 10.f; lsum += LOGC - 0.5f * z * z; }
                    }
                    const int r1 = r0 + 8;
                    if (r1 < TLTOT) {
                        float2 rv = __ldcs((const float2*)(R + (size_t)r1 * NTOP + jc));
                        int2   cv = __ldcs((const int2*)(C + (size_t)r1 * NTOP + jc));
                        if (cv.x == 1) { float m = sigmoidf(a[2]); float z = (rv.x - m) * 10.f; lsum += LOGC - 0.5f * z * z; }
                        if (cv.y == 1) { float m = sigmoidf(a[3]); float z = (rv.y - m) * 10.f; lsum += LOGC - 0.5f * z * z; }
                    }
                }
            }
        }
    }

    // ---- reduction ----
    #pragma unroll
    for (int o = 16; o > 0; o >>= 1)
        lsum += __shfl_xor_sync(0xFFFFFFFFu, lsum, o);
    if (lane == 0) red[warp] = lsum;
    __syncthreads();
    if (warp == 0) {
        float v = (lane < 8) ? red[lane] : 0.f;
        #pragma unroll
        for (int o = 4; o > 0; o >>= 1)
            v += __shfl_xor_sync(0xFFFFFFFFu, v, o);
        if (lane == 0) atomicAdd(out, v);
    }
}

// ---------------------------------------------------------------------------
extern "C" void kernel_launch(void* const* d_in, const int* in_sizes, int n_in,
                              void* d_out, int out_size)
{
    // Identify inputs by element count (dict order breaks the two ties:
    // V before noise at 256000, R before C at 40000000).
    //   Q: (1000,32)=32000            V: (1000,256)=256000
    //   R: (20,2000,1000)=40000000    nw: (1000,1000)=1000000
    //   U: (20,2000,256,5)=51200000   W: (1,5)=5   b: (1,)=1
    //   noise: (1000,256)=256000      C: (20,2000,1000)=40000000
    const float *V = nullptr, *R = nullptr, *nw = nullptr, *U = nullptr;
    const float *W = nullptr, *Bb = nullptr, *noise = nullptr;
    const int* C = nullptr;
    int seen256k = 0, seen40m = 0;
    for (int i = 0; i < n_in; i++) {
        switch (in_sizes[i]) {
            case 256000:
                if (seen256k++ == 0) V = (const float*)d_in[i];
                else                 noise = (const float*)d_in[i];
                break;
            case 40000000:
                if (seen40m++ == 0) R = (const float*)d_in[i];
                else                C = (const int*)d_in[i];
                break;
            case 1000000:  nw = (const float*)d_in[i]; break;
            case 51200000: U  = (const float*)d_in[i]; break;
            case 5:        W  = (const float*)d_in[i]; break;
            case 1:        Bb = (const float*)d_in[i]; break;
            default: break; // Q (32000) unused
        }
    }
    float* out = (float*)d_out;

    cudaFuncSetAttribute(main_kernel, cudaFuncAttributeMaxDynamicSharedMemorySize, SMEM_BYTES);

    setup_kernel<<<4, 256>>>(V, nw, noise, out);
    main_kernel<<<(TLTOT + BM - 1) / BM, 256, SMEM_BYTES>>>(R, U, W, Bb, C, out);
}

// round 6
// speedup vs baseline: 1.5732x; 1.5732x over previous
#include <cuda_runtime.h>
#include <cuda_bf16.h>
#include <cstdint>
#include <cstdio>

#define TLTOT 40000
#define NTOP  1000
#define KCDIM 256
#define BM    128
#define BN    64
#define PITCH 264   // bf16 elems per SMEM row (256 + 8 pad -> 528B, LDSM conflict-free)

#define SMEM_BYTES ((BM*PITCH*2)*2 + (BN*PITCH*2)*2)   // A_hi,A_lo,B_hi,B_lo = 202752

// -log(0.1) - 0.5*log(2*pi)
#define LOGC 1.3836465597893728f

__device__ __nv_bfloat16 g_Bhi[NTOP * KCDIM];
__device__ __nv_bfloat16 g_Blo[NTOP * KCDIM];

// ---------------------------------------------------------------------------
// Kernel 1 (coalesced): column-sums of nw, build split-bf16 V_j, zero d_out
// Grid 32 x 256: block b owns columns [b*32, b*32+32); lanes span 32 adjacent
// columns (coalesced 128B rows); 8 row-groups of partial sums, SMEM-reduced.
// ---------------------------------------------------------------------------
__global__ void setup_kernel(const float* __restrict__ V,
                             const float* __restrict__ nw,
                             const float* __restrict__ noise,
                             float* __restrict__ out)
{
    __shared__ float s_part[8][32];
    __shared__ float s_sum[32];
    const int t    = threadIdx.x;
    const int b    = blockIdx.x;
    const int cl   = t & 31;          // column within block's 32
    const int rg   = t >> 5;          // row group 0..7
    const int col  = b * 32 + cl;

    float s = 0.f;
    if (col < NTOP) {
        for (int i = rg; i < NTOP; i += 8)
            s += nw[i * NTOP + col];
    }
    s_part[rg][cl] = s;
    __syncthreads();
    if (rg == 0) {
        float v = s_part[0][cl];
        #pragma unroll
        for (int g = 1; g < 8; g++) v += s_part[g][cl];
        s_sum[cl] = v;
    }
    __syncthreads();

    // fill 32 cols x 256 k  (8192 elems, 256 threads -> 32 iters, k-coalesced)
    for (int idx = t; idx < 32 * KCDIM; idx += 256) {
        int jl = idx >> 8;            // 0..31
        int k  = idx & 255;
        int jg = b * 32 + jl;
        if (jg < NTOP) {
            int g = jg * KCDIM + k;
            float v = fmaf(V[g], s_sum[jl], 0.1f * noise[g]);
            __nv_bfloat16 h = __float2bfloat16(v);
            g_Bhi[g] = h;
            g_Blo[g] = __float2bfloat16(v - __bfloat162float(h));
        }
    }
    if (b == 0 && t == 0) *out = 0.f;
}

// ---------------------------------------------------------------------------
// MMA helpers
// ---------------------------------------------------------------------------
__device__ __forceinline__ void ldsm4(uint32_t* r, uint32_t saddr) {
    asm volatile("ldmatrix.sync.aligned.m8n8.x4.shared.b16 {%0,%1,%2,%3}, [%4];\n"
                 : "=r"(r[0]), "=r"(r[1]), "=r"(r[2]), "=r"(r[3]) : "r"(saddr));
}

__device__ __forceinline__ void mma16816(float* c, const uint32_t* a, uint32_t b0, uint32_t b1) {
    asm volatile(
        "mma.sync.aligned.m16n8k16.row.col.f32.bf16.bf16.f32 "
        "{%0,%1,%2,%3},{%4,%5,%6,%7},{%8,%9},{%0,%1,%2,%3};\n"
        : "+f"(c[0]), "+f"(c[1]), "+f"(c[2]), "+f"(c[3])
        : "r"(a[0]), "r"(a[1]), "r"(a[2]), "r"(a[3]), "r"(b0), "r"(b1));
}

__device__ __forceinline__ float sigmoidf(float x) {
    return __fdividef(1.f, 1.f + __expf(-x));
}

// ---------------------------------------------------------------------------
// Kernel 2: fused U_emb + split-bf16 GEMM + sigmoid + masked logprob
// 512 threads: 4 warps over M (32 rows) x 4 warps over N (16 cols).
// R/C for each tile are prefetched into registers BEFORE the MMA loop so the
// DRAM latency is hidden behind tensor work.
// ---------------------------------------------------------------------------
__global__ void __launch_bounds__(512, 1)
main_kernel(const float* __restrict__ R,
            const float* __restrict__ U,
            const float* __restrict__ W,
            const float* __restrict__ Bb,
            const int*   __restrict__ C,
            float* __restrict__ out)
{
    extern __shared__ __align__(16) char smem[];
    __nv_bfloat16* Ah = (__nv_bfloat16*)smem;          // [BM][PITCH]
    __nv_bfloat16* Al = Ah + BM * PITCH;
    __nv_bfloat16* Bh = Al + BM * PITCH;               // [BN][PITCH]
    __nv_bfloat16* Bl = Bh + BN * PITCH;
    __shared__ float red[16];

    const int tid  = threadIdx.x;
    const int lane = tid & 31;
    const int warp = tid >> 5;
    const int wm   = warp & 3;    // 4 warps over M (32 rows each)
    const int wn   = warp >> 2;   // 4 warps over N (16 cols each)
    const int rowbase = blockIdx.x * BM;

    const float w0 = W[0], w1 = W[1], w2 = W[2], w3 = W[3], w4 = W[4];
    const float bb = Bb[0];

    // ---- Phase 1: U_emb (fp32) -> split bf16 A tile (64 iters/thread) ----
    for (int idx = tid; idx < BM * KCDIM; idx += 512) {
        int r = idx >> 8;
        int k = idx & 255;
        int gr = rowbase + r;
        float v = 0.f;
        if (gr < TLTOT) {
            const float* up = U + ((size_t)gr * (KCDIM * 5) + k * 5);
            v = bb;
            v = fmaf(__ldcs(up + 0), w0, v);
            v = fmaf(__ldcs(up + 1), w1, v);
            v = fmaf(__ldcs(up + 2), w2, v);
            v = fmaf(__ldcs(up + 3), w3, v);
            v = fmaf(__ldcs(up + 4), w4, v);
        }
        __nv_bfloat16 h = __float2bfloat16(v);
        Ah[r * PITCH + k] = h;
        Al[r * PITCH + k] = __float2bfloat16(v - __bfloat162float(h));
    }

    const uint32_t sbase = (uint32_t)__cvta_generic_to_shared(smem);
    const uint32_t sAh = sbase;
    const uint32_t sAl = sAh + BM * PITCH * 2;
    const uint32_t sBh = sAl + BM * PITCH * 2;
    const uint32_t sBl = sBh + BN * PITCH * 2;

    // per-lane ldmatrix addresses (bytes)
    const uint32_t arow = ((uint32_t)(wm * 32 + (lane & 15)) * PITCH + (uint32_t)(lane >> 4) * 8) * 2;
    const uint32_t boff = ((uint32_t)(wn * 16 + ((lane >> 4) & 1) * 8 + (lane & 7)) * PITCH
                           + (uint32_t)((lane >> 3) & 1) * 8) * 2;

    // epilogue coordinates (fixed per thread)
    const int er0 = rowbase + wm * 32 + (lane >> 2);      // +mi*16, +8
    const int ejc = wn * 16 + ((lane & 3) << 1);          // +j0, +ni*8

    float lsum = 0.f;

    for (int j0 = 0; j0 < NTOP; j0 += BN) {
        __syncthreads();   // prev tile's B reads done (also fences phase-1 A writes)

        // ---- stage B tiles (16B vectors, 4 iters/thread) ----
        for (int v = tid; v < BN * (KCDIM / 8); v += 512) {
            int n  = v >> 5;
            int c8 = v & 31;
            int jj = j0 + n;
            uint4 hv = make_uint4(0, 0, 0, 0), lv = make_uint4(0, 0, 0, 0);
            if (jj < NTOP) {
                hv = *(const uint4*)(g_Bhi + jj * KCDIM + c8 * 8);
                lv = *(const uint4*)(g_Blo + jj * KCDIM + c8 * 8);
            }
            *(uint4*)(Bh + n * PITCH + c8 * 8) = hv;
            *(uint4*)(Bl + n * PITCH + c8 * 8) = lv;
        }
        __syncthreads();

        // ---- prefetch R/C for this tile (latency hidden behind MMA) ----
        float2 rv[2][2][2];
        int2   cv[2][2][2];
        #pragma unroll
        for (int mi = 0; mi < 2; mi++) {
            #pragma unroll
            for (int ni = 0; ni < 2; ni++) {
                #pragma unroll
                for (int rr = 0; rr < 2; rr++) {
                    cv[mi][ni][rr] = make_int2(0, 0);
                    const int row = er0 + mi * 16 + rr * 8;
                    const int jc  = j0 + ejc + ni * 8;
                    if (row < TLTOT && jc < NTOP) {
                        const size_t off = (size_t)row * NTOP + jc;
                        rv[mi][ni][rr] = __ldcs((const float2*)(R + off));
                        cv[mi][ni][rr] = __ldcs((const int2*)(C + off));
                    }
                }
            }
        }

        // ---- MMA: acc = Ah*Bh + Al*Bh + Ah*Bl ----
        float acc[2][2][4] = {};
        #pragma unroll 4
        for (int ks = 0; ks < 16; ks++) {
            const uint32_t k0b = (uint32_t)(ks * 16) * 2;
            uint32_t ah[2][4], al[2][4], bh[4], bl[4];
            ldsm4(ah[0], sAh + arow + k0b);
            ldsm4(ah[1], sAh + arow + 16 * PITCH * 2 + k0b);
            ldsm4(al[0], sAl + arow + k0b);
            ldsm4(al[1], sAl + arow + 16 * PITCH * 2 + k0b);
            ldsm4(bh, sBh + boff + k0b);
            ldsm4(bl, sBl + boff + k0b);
            #pragma unroll
            for (int mi = 0; mi < 2; mi++) {
                #pragma unroll
                for (int ni = 0; ni < 2; ni++) {
                    const int s = ni * 2;
                    mma16816(acc[mi][ni], ah[mi], bh[s], bh[s + 1]);
                    mma16816(acc[mi][ni], al[mi], bh[s], bh[s + 1]);
                    mma16816(acc[mi][ni], ah[mi], bl[s], bl[s + 1]);
                }
            }
        }

        // ---- consume: sigmoid + masked Normal logprob ----
        #pragma unroll
        for (int mi = 0; mi < 2; mi++) {
            #pragma unroll
            for (int ni = 0; ni < 2; ni++) {
                const float* a = acc[mi][ni];
                #pragma unroll
                for (int rr = 0; rr < 2; rr++) {
                    const float2 r2 = rv[mi][ni][rr];
                    const int2   c2 = cv[mi][ni][rr];
                    if (c2.x == 1) { float m = sigmoidf(a[rr * 2 + 0]); float z = (r2.x - m) * 10.f; lsum += LOGC - 0.5f * z * z; }
                    if (c2.y == 1) { float m = sigmoidf(a[rr * 2 + 1]); float z = (r2.y - m) * 10.f; lsum += LOGC - 0.5f * z * z; }
                }
            }
        }
    }

    // ---- reduction ----
    #pragma unroll
    for (int o = 16; o > 0; o >>= 1)
        lsum += __shfl_xor_sync(0xFFFFFFFFu, lsum, o);
    if (lane == 0) red[warp] = lsum;
    __syncthreads();
    if (warp == 0) {
        float v = (lane < 16) ? red[lane] : 0.f;
        #pragma unroll
        for (int o = 8; o > 0; o >>= 1)
            v += __shfl_xor_sync(0xFFFFFFFFu, v, o);
        if (lane == 0) atomicAdd(out, v);
    }
}

// ---------------------------------------------------------------------------
extern "C" void kernel_launch(void* const* d_in, const int* in_sizes, int n_in,
                              void* d_out, int out_size)
{
    // Identify inputs by element count (dict order breaks the two ties:
    // V before noise at 256000, R before C at 40000000).
    //   Q: 32000  V: 256000  R: 40000000  nw: 1000000
    //   U: 51200000  W: 5  b: 1  noise: 256000  C: 40000000
    const float *V = nullptr, *R = nullptr, *nw = nullptr, *U = nullptr;
    const float *W = nullptr, *Bb = nullptr, *noise = nullptr;
    const int* C = nullptr;
    int seen256k = 0, seen40m = 0;
    for (int i = 0; i < n_in; i++) {
        switch (in_sizes[i]) {
            case 256000:
                if (seen256k++ == 0) V = (const float*)d_in[i];
                else                 noise = (const float*)d_in[i];
                break;
            case 40000000:
                if (seen40m++ == 0) R = (const float*)d_in[i];
                else                C = (const int*)d_in[i];
                break;
            case 1000000:  nw = (const float*)d_in[i]; break;
            case 51200000: U  = (const float*)d_in[i]; break;
            case 5:        W  = (const float*)d_in[i]; break;
            case 1:        Bb = (const float*)d_in[i]; break;
            default: break; // Q unused
        }
    }
    float* out = (float*)d_out;

    cudaFuncSetAttribute(main_kernel, cudaFuncAttributeMaxDynamicSharedMemorySize, SMEM_BYTES);

    setup_kernel<<<32, 256>>>(V, nw, noise, out);
    main_kernel<<<(TLTOT + BM - 1) / BM, 512, SMEM_BYTES>>>(R, U, W, Bb, C, out);
}

// round 7
// speedup vs baseline: 1.6047x; 1.0201x over previous
#include <cuda_runtime.h>
#include <cuda_bf16.h>
#include <cstdint>
#include <cstdio>

#define TLTOT 40000
#define NTOP  1000
#define KCDIM 256
#define BM    128
#define BN    64
#define PITCH 264   // bf16 elems per SMEM row (256 + 8 pad -> 528B, LDSM conflict-free)

#define SMEM_BYTES ((BM*PITCH*2)*2 + (BN*PITCH*2)*2)   // A_hi,A_lo,B_hi,B_lo = 202752

// -log(0.1) - 0.5*log(2*pi)
#define LOGC 1.3836465597893728f

__device__ __nv_bfloat16 g_Bhi[NTOP * KCDIM];
__device__ __nv_bfloat16 g_Blo[NTOP * KCDIM];

// ---------------------------------------------------------------------------
// Kernel 1 (coalesced): column-sums of nw, build split-bf16 V_j, zero d_out
// ---------------------------------------------------------------------------
__global__ void setup_kernel(const float* __restrict__ V,
                             const float* __restrict__ nw,
                             const float* __restrict__ noise,
                             float* __restrict__ out)
{
    __shared__ float s_part[8][32];
    __shared__ float s_sum[32];
    const int t    = threadIdx.x;
    const int b    = blockIdx.x;
    const int cl   = t & 31;          // column within block's 32
    const int rg   = t >> 5;          // row group 0..7
    const int col  = b * 32 + cl;

    float s = 0.f;
    if (col < NTOP) {
        for (int i = rg; i < NTOP; i += 8)
            s += nw[i * NTOP + col];
    }
    s_part[rg][cl] = s;
    __syncthreads();
    if (rg == 0) {
        float v = s_part[0][cl];
        #pragma unroll
        for (int g = 1; g < 8; g++) v += s_part[g][cl];
        s_sum[cl] = v;
    }
    __syncthreads();

    for (int idx = t; idx < 32 * KCDIM; idx += 256) {
        int jl = idx >> 8;
        int k  = idx & 255;
        int jg = b * 32 + jl;
        if (jg < NTOP) {
            int g = jg * KCDIM + k;
            float v = fmaf(V[g], s_sum[jl], 0.1f * noise[g]);
            __nv_bfloat16 h = __float2bfloat16(v);
            g_Bhi[g] = h;
            g_Blo[g] = __float2bfloat16(v - __bfloat162float(h));
        }
    }
    if (b == 0 && t == 0) *out = 0.f;
}

// ---------------------------------------------------------------------------
// MMA helpers
// ---------------------------------------------------------------------------
__device__ __forceinline__ void ldsm4(uint32_t* r, uint32_t saddr) {
    asm volatile("ldmatrix.sync.aligned.m8n8.x4.shared.b16 {%0,%1,%2,%3}, [%4];\n"
                 : "=r"(r[0]), "=r"(r[1]), "=r"(r[2]), "=r"(r[3]) : "r"(saddr));
}

__device__ __forceinline__ void mma16816(float* c, const uint32_t* a, uint32_t b0, uint32_t b1) {
    asm volatile(
        "mma.sync.aligned.m16n8k16.row.col.f32.bf16.bf16.f32 "
        "{%0,%1,%2,%3},{%4,%5,%6,%7},{%8,%9},{%0,%1,%2,%3};\n"
        : "+f"(c[0]), "+f"(c[1]), "+f"(c[2]), "+f"(c[3])
        : "r"(a[0]), "r"(a[1]), "r"(a[2]), "r"(a[3]), "r"(b0), "r"(b1));
}

__device__ __forceinline__ float sigmoidf(float x) {
    return __fdividef(1.f, 1.f + __expf(-x));
}

// ---------------------------------------------------------------------------
// Kernel 2: fused U_emb + split-bf16 GEMM + sigmoid + masked logprob
// 1024 threads / 32 warps: 8 warps over M (16 rows) x 4 warps over N (16 cols).
// R/C prefetched before B staging so DRAM latency hides behind stage+MMA.
// ---------------------------------------------------------------------------
__global__ void __launch_bounds__(1024, 1)
main_kernel(const float* __restrict__ R,
            const float* __restrict__ U,
            const float* __restrict__ W,
            const float* __restrict__ Bb,
            const int*   __restrict__ C,
            float* __restrict__ out)
{
    extern __shared__ __align__(16) char smem[];
    __nv_bfloat16* Ah = (__nv_bfloat16*)smem;          // [BM][PITCH]
    __nv_bfloat16* Al = Ah + BM * PITCH;
    __nv_bfloat16* Bh = Al + BM * PITCH;               // [BN][PITCH]
    __nv_bfloat16* Bl = Bh + BN * PITCH;
    __shared__ float red[32];

    const int tid  = threadIdx.x;
    const int lane = tid & 31;
    const int warp = tid >> 5;
    const int wm   = warp & 7;    // 8 warps over M (16 rows each)
    const int wn   = warp >> 3;   // 4 warps over N (16 cols each)
    const int rowbase = blockIdx.x * BM;

    const float w0 = W[0], w1 = W[1], w2 = W[2], w3 = W[3], w4 = W[4];
    const float bb = Bb[0];

    // ---- Phase 1: U_emb (fp32) -> split bf16 A tile (32 iters/thread) ----
    for (int idx = tid; idx < BM * KCDIM; idx += 1024) {
        int r = idx >> 8;
        int k = idx & 255;
        int gr = rowbase + r;
        float v = 0.f;
        if (gr < TLTOT) {
            const float* up = U + ((size_t)gr * (KCDIM * 5) + k * 5);
            v = bb;
            v = fmaf(__ldcs(up + 0), w0, v);
            v = fmaf(__ldcs(up + 1), w1, v);
            v = fmaf(__ldcs(up + 2), w2, v);
            v = fmaf(__ldcs(up + 3), w3, v);
            v = fmaf(__ldcs(up + 4), w4, v);
        }
        __nv_bfloat16 h = __float2bfloat16(v);
        Ah[r * PITCH + k] = h;
        Al[r * PITCH + k] = __float2bfloat16(v - __bfloat162float(h));
    }

    const uint32_t sbase = (uint32_t)__cvta_generic_to_shared(smem);
    const uint32_t sAh = sbase;
    const uint32_t sAl = sAh + BM * PITCH * 2;
    const uint32_t sBh = sAl + BM * PITCH * 2;
    const uint32_t sBl = sBh + BN * PITCH * 2;

    // per-lane ldmatrix addresses (bytes)
    const uint32_t arow = ((uint32_t)(wm * 16 + (lane & 15)) * PITCH + (uint32_t)(lane >> 4) * 8) * 2;
    const uint32_t boff = ((uint32_t)(wn * 16 + ((lane >> 4) & 1) * 8 + (lane & 7)) * PITCH
                           + (uint32_t)((lane >> 3) & 1) * 8) * 2;

    // epilogue coordinates (fixed per thread)
    const int er0 = rowbase + wm * 16 + (lane >> 2);      // rows er0, er0+8
    const int ejc = wn * 16 + ((lane & 3) << 1);          // +j0, +ni*8

    float lsum = 0.f;

    for (int j0 = 0; j0 < NTOP; j0 += BN) {
        // ---- prefetch R/C for this tile (latency hidden behind stage+MMA) ----
        float2 rv[2][2];
        int2   cv[2][2];
        #pragma unroll
        for (int ni = 0; ni < 2; ni++) {
            #pragma unroll
            for (int rr = 0; rr < 2; rr++) {
                cv[ni][rr] = make_int2(0, 0);
                const int row = er0 + rr * 8;
                const int jc  = j0 + ejc + ni * 8;
                if (row < TLTOT && jc < NTOP) {
                    const size_t off = (size_t)row * NTOP + jc;
                    rv[ni][rr] = __ldcs((const float2*)(R + off));
                    cv[ni][rr] = __ldcs((const int2*)(C + off));
                }
            }
        }

        __syncthreads();   // prev tile's B reads done (also fences phase-1 A writes)

        // ---- stage B tiles (16B vectors, 2 iters/thread) ----
        for (int v = tid; v < BN * (KCDIM / 8); v += 1024) {
            int n  = v >> 5;
            int c8 = v & 31;
            int jj = j0 + n;
            uint4 hv = make_uint4(0, 0, 0, 0), lv = make_uint4(0, 0, 0, 0);
            if (jj < NTOP) {
                hv = *(const uint4*)(g_Bhi + jj * KCDIM + c8 * 8);
                lv = *(const uint4*)(g_Blo + jj * KCDIM + c8 * 8);
            }
            *(uint4*)(Bh + n * PITCH + c8 * 8) = hv;
            *(uint4*)(Bl + n * PITCH + c8 * 8) = lv;
        }
        __syncthreads();

        // ---- MMA: acc = Ah*Bh + Al*Bh + Ah*Bl ----
        float acc[2][4] = {};
        #pragma unroll 4
        for (int ks = 0; ks < 16; ks++) {
            const uint32_t k0b = (uint32_t)(ks * 16) * 2;
            uint32_t ah[4], al[4], bh[4], bl[4];
            ldsm4(ah, sAh + arow + k0b);
            ldsm4(al, sAl + arow + k0b);
            ldsm4(bh, sBh + boff + k0b);
            ldsm4(bl, sBl + boff + k0b);
            #pragma unroll
            for (int ni = 0; ni < 2; ni++) {
                const int s = ni * 2;
                mma16816(acc[ni], ah, bh[s], bh[s + 1]);
                mma16816(acc[ni], al, bh[s], bh[s + 1]);
                mma16816(acc[ni], ah, bl[s], bl[s + 1]);
            }
        }

        // ---- consume: sigmoid + masked Normal logprob ----
        #pragma unroll
        for (int ni = 0; ni < 2; ni++) {
            const float* a = acc[ni];
            #pragma unroll
            for (int rr = 0; rr < 2; rr++) {
                const float2 r2 = rv[ni][rr];
                const int2   c2 = cv[ni][rr];
                if (c2.x == 1) { float m = sigmoidf(a[rr * 2 + 0]); float z = (r2.x - m) * 10.f; lsum += LOGC - 0.5f * z * z; }
                if (c2.y == 1) { float m = sigmoidf(a[rr * 2 + 1]); float z = (r2.y - m) * 10.f; lsum += LOGC - 0.5f * z * z; }
            }
        }
    }

    // ---- reduction ----
    #pragma unroll
    for (int o = 16; o > 0; o >>= 1)
        lsum += __shfl_xor_sync(0xFFFFFFFFu, lsum, o);
    if (lane == 0) red[warp] = lsum;
    __syncthreads();
    if (warp == 0) {
        float v = red[lane];
        #pragma unroll
        for (int o = 16; o > 0; o >>= 1)
            v += __shfl_xor_sync(0xFFFFFFFFu, v, o);
        if (lane == 0) atomicAdd(out, v);
    }
}

// ---------------------------------------------------------------------------
extern "C" void kernel_launch(void* const* d_in, const int* in_sizes, int n_in,
                              void* d_out, int out_size)
{
    // Identify inputs by element count (dict order breaks the two ties:
    // V before noise at 256000, R before C at 40000000).
    const float *V = nullptr, *R = nullptr, *nw = nullptr, *U = nullptr;
    const float *W = nullptr, *Bb = nullptr, *noise = nullptr;
    const int* C = nullptr;
    int seen256k = 0, seen40m = 0;
    for (int i = 0; i < n_in; i++) {
        switch (in_sizes[i]) {
            case 256000:
                if (seen256k++ == 0) V = (const float*)d_in[i];
                else                 noise = (const float*)d_in[i];
                break;
            case 40000000:
                if (seen40m++ == 0) R = (const float*)d_in[i];
                else                C = (const int*)d_in[i];
                break;
            case 1000000:  nw = (const float*)d_in[i]; break;
            case 51200000: U  = (const float*)d_in[i]; break;
            case 5:        W  = (const float*)d_in[i]; break;
            case 1:        Bb = (const float*)d_in[i]; break;
            default: break; // Q unused
        }
    }
    float* out = (float*)d_out;

    cudaFuncSetAttribute(main_kernel, cudaFuncAttributeMaxDynamicSharedMemorySize, SMEM_BYTES);

    setup_kernel<<<32, 256>>>(V, nw, noise, out);
    main_kernel<<<(TLTOT + BM - 1) / BM, 1024, SMEM_BYTES>>>(R, U, W, Bb, C, out);
}